// round 1
// baseline (speedup 1.0000x reference)
#include <cuda_runtime.h>
#include <math.h>

// ---------------------------------------------------------------------------
// BiFormer block, fp32 baseline.
// Layouts: "window" rows  r = (n*49 + p)*64 + q   (p = window, q = pixel-in-window)
//          "image"  rows  r = n*3136 + y*56 + x
// Pipeline: LN1 -> QKV gemm -> window means -> routing top-4 -> attention
//           -> lepe dwconv -> (attn+lepe)@Wo + x -> LN2 -> MLP1(gelu) -> MLP2 + x1
// ---------------------------------------------------------------------------

#define NB    8
#define HWDIM 56
#define CDIM  256
#define QKD   256
#define NHEAD 8
#define DHEAD 32
#define P2    49
#define W2    64
#define TOPK  4
#define NPIX  (NB*HWDIM*HWDIM)     // 25088
#define QKVC  768
#define HIDD  1024
#define ATTN_SCALE 0.0625f         // 256^-0.5

// scratch (device globals; no allocation allowed)
__device__ float g_xln [NPIX*CDIM];
__device__ float g_qkv [NPIX*QKVC];
__device__ float g_qkwin[NB*P2*512];
__device__ int   g_ridx[NB*P2*TOPK];
__device__ float g_lepe[NPIX*CDIM];
__device__ float g_attn[NPIX*CDIM];
__device__ float g_x1  [NPIX*CDIM];
__device__ float g_hln [NPIX*CDIM];
__device__ float g_hid [NPIX*HIDD];

__device__ __forceinline__ int img_from_win(int r) {
    int n   = r / 3136;
    int rem = r - n * 3136;
    int p = rem >> 6, q = rem & 63;
    int y = ((p / 7) << 3) | (q >> 3);
    int x = ((p % 7) << 3) | (q & 7);
    return n * 3136 + y * 56 + x;
}
__device__ __forceinline__ int win_from_img(int n, int y, int x) {
    int p = (y >> 3) * 7 + (x >> 3);
    int q = ((y & 7) << 3) | (x & 7);
    return (n * 49 + p) * 64 + q;
}

// ---------------- LayerNorm (block = one output row in window layout) -------
template<bool REMAP_IN>
__global__ __launch_bounds__(256) void ln_kernel(
    const float* __restrict__ in, const float* __restrict__ gam,
    const float* __restrict__ bet, float* __restrict__ out)
{
    int r = blockIdx.x, c = threadIdx.x;
    int ir = REMAP_IN ? img_from_win(r) : r;
    float v = in[(size_t)ir * CDIM + c];

    __shared__ float red1[8], red2[8];
    float s = v, s2 = v * v;
    #pragma unroll
    for (int o = 16; o; o >>= 1) {
        s  += __shfl_xor_sync(0xffffffffu, s,  o);
        s2 += __shfl_xor_sync(0xffffffffu, s2, o);
    }
    if ((c & 31) == 0) { red1[c >> 5] = s; red2[c >> 5] = s2; }
    __syncthreads();
    if (c == 0) {
        float t1 = 0.f, t2 = 0.f;
        #pragma unroll
        for (int i = 0; i < 8; i++) { t1 += red1[i]; t2 += red2[i]; }
        float mu = t1 * (1.f / CDIM);
        red1[0] = mu;
        red2[0] = t2 * (1.f / CDIM) - mu * mu;   // E[x^2]-mu^2
    }
    __syncthreads();
    float mu = red1[0], var = red2[0];
    out[(size_t)r * CDIM + c] = (v - mu) * rsqrtf(var + 1e-6f) * gam[c] + bet[c];
}

// ---------------- SGEMM: out = A(+A2) @ W + bias, with epilogue variants ----
#define BM 128
#define BN 64
#define BK 16
#define EPI_NONE 0
#define EPI_GELU 1
#define EPI_WO   2   // += res[img_from_win(row)]      (residual x, image layout)
#define EPI_OUT  3   // += res[row]; store to img row  (final output)

template<int EPI, bool ADDA>
__global__ __launch_bounds__(256) void sgemm_kernel(
    const float* __restrict__ A, const float* __restrict__ A2,
    const float* __restrict__ W, const float* __restrict__ bias,
    const float* __restrict__ res, float* __restrict__ out,
    int M, int N, int K)
{
    __shared__ float As[BK][BM];
    __shared__ float Bs[BK][BN];
    int t = threadIdx.x;
    int bm = blockIdx.y * BM, bn = blockIdx.x * BN;
    int trow = t >> 4, tcol = t & 15;

    float acc[8][4];
    #pragma unroll
    for (int i = 0; i < 8; i++)
        #pragma unroll
        for (int j = 0; j < 4; j++) acc[i][j] = 0.f;

    for (int k0 = 0; k0 < K; k0 += BK) {
        #pragma unroll
        for (int l = 0; l < 2; l++) {
            int id = t + l * 256;
            int ar = id >> 2, ac = (id & 3) << 2;
            const float4 v = *(const float4*)(A + (size_t)(bm + ar) * K + k0 + ac);
            float vx = v.x, vy = v.y, vz = v.z, vw = v.w;
            if (ADDA) {
                const float4 v2 = *(const float4*)(A2 + (size_t)(bm + ar) * K + k0 + ac);
                vx += v2.x; vy += v2.y; vz += v2.z; vw += v2.w;
            }
            As[ac + 0][ar] = vx; As[ac + 1][ar] = vy;
            As[ac + 2][ar] = vz; As[ac + 3][ar] = vw;
        }
        {
            int br = t >> 4, bc = (t & 15) << 2;
            *(float4*)&Bs[br][bc] = *(const float4*)(W + (size_t)(k0 + br) * N + bn + bc);
        }
        __syncthreads();
        #pragma unroll
        for (int kk = 0; kk < BK; kk++) {
            float a[8], b[4];
            *(float4*)&a[0] = *(const float4*)&As[kk][trow * 8];
            *(float4*)&a[4] = *(const float4*)&As[kk][trow * 8 + 4];
            *(float4*)&b[0] = *(const float4*)&Bs[kk][tcol * 4];
            #pragma unroll
            for (int i = 0; i < 8; i++)
                #pragma unroll
                for (int j = 0; j < 4; j++)
                    acc[i][j] += a[i] * b[j];
        }
        __syncthreads();
    }

    #pragma unroll
    for (int i = 0; i < 8; i++) {
        int row  = bm + trow * 8 + i;
        int colb = bn + tcol * 4;
        float vb[4];
        #pragma unroll
        for (int j = 0; j < 4; j++) vb[j] = acc[i][j] + bias[colb + j];
        if (EPI == EPI_GELU) {
            #pragma unroll
            for (int j = 0; j < 4; j++)
                vb[j] = 0.5f * vb[j] * (1.f + erff(vb[j] * 0.70710678118654752f));
        }
        if (EPI == EPI_WO) {
            int ir = img_from_win(row);
            const float4 rv = *(const float4*)(res + (size_t)ir * N + colb);
            vb[0] += rv.x; vb[1] += rv.y; vb[2] += rv.z; vb[3] += rv.w;
        }
        if (EPI == EPI_OUT) {
            const float4 rv = *(const float4*)(res + (size_t)row * N + colb);
            vb[0] += rv.x; vb[1] += rv.y; vb[2] += rv.z; vb[3] += rv.w;
        }
        int orow = (EPI == EPI_OUT) ? img_from_win(row) : row;
        float4 ov; ov.x = vb[0]; ov.y = vb[1]; ov.z = vb[2]; ov.w = vb[3];
        *(float4*)(out + (size_t)orow * N + colb) = ov;
    }
}

// ---------------- window means of q,k -> g_qkwin ----------------------------
__global__ __launch_bounds__(512) void winmean_kernel()
{
    int np = blockIdx.x;            // n*49+p
    int c  = threadIdx.x;           // 0..511 (q:0..255, k:256..511)
    const float* base = g_qkv + (size_t)np * 64 * QKVC;
    float s = 0.f;
    #pragma unroll 8
    for (int q = 0; q < 64; q++) s += base[q * QKVC + c];
    g_qkwin[(size_t)np * 512 + c] = s * (1.f / 64.f);
}

// ---------------- routing: 49x49 logits, top-4 per row ----------------------
__global__ __launch_bounds__(256) void route_kernel()
{
    int n = blockIdx.x, t = threadIdx.x;
    __shared__ float lg[P2 * P2];
    for (int e = t; e < P2 * P2; e += 256) {
        int p = e / 49, pp = e - p * 49;
        const float* qw = g_qkwin + (size_t)(n * 49 + p)  * 512;
        const float* kw = g_qkwin + (size_t)(n * 49 + pp) * 512 + 256;
        float s = 0.f;
        #pragma unroll 8
        for (int c = 0; c < 256; c++) s += qw[c] * kw[c];
        lg[e] = s;                                 // scale irrelevant for ranking
    }
    __syncthreads();
    if (t < P2) {
        const float* row = lg + t * 49;
        int sel[4] = {-1, -1, -1, -1};
        #pragma unroll
        for (int k = 0; k < 4; k++) {
            float best = -3.4e38f; int bi = 0;
            for (int i = 0; i < 49; i++) {
                if (i == sel[0] || i == sel[1] || i == sel[2] || i == sel[3]) continue;
                if (row[i] > best) { best = row[i]; bi = i; }
            }
            sel[k] = bi;
            g_ridx[(n * 49 + t) * 4 + k] = bi;
        }
    }
}

// ---------------- lepe: 5x5 depthwise conv on v, SAME padding ---------------
__global__ __launch_bounds__(256) void lepe_kernel(
    const float* __restrict__ w, const float* __restrict__ b)
{
    int pix = blockIdx.x, c = threadIdx.x;
    int n = pix / 3136; int rem = pix - n * 3136;
    int y = rem / 56, x = rem - y * 56;
    float acc = b[c];
    #pragma unroll
    for (int dy = 0; dy < 5; dy++) {
        int yy = y + dy - 2;
        if (yy < 0 || yy >= 56) continue;
        #pragma unroll
        for (int dx = 0; dx < 5; dx++) {
            int xx = x + dx - 2;
            if (xx < 0 || xx >= 56) continue;
            int wr = win_from_img(n, yy, xx);
            acc += w[(dy * 5 + dx) * CDIM + c] * g_qkv[(size_t)wr * QKVC + 512 + c];
        }
    }
    g_lepe[(size_t)win_from_img(n, y, x) * CDIM + c] = acc;
}

// ---------------- attention: block = (n,p,head) -----------------------------
// smem: qs[64][33], kvs[256][33] (k then reused for v), S[64][257]
#define ATTN_SMEM ((64*33 + 256*33 + 64*257) * 4)

__global__ __launch_bounds__(256) void attn_kernel()
{
    extern __shared__ float sm[];
    float* qs  = sm;                  // 64*33
    float* kvs = sm + 64 * 33;        // 256*33
    float* S   = kvs + 256 * 33;      // 64*257

    int blk = blockIdx.x;
    int m  = blk & 7;
    int np = blk >> 3;                // n*49 + p
    int n  = np / 49;
    int t  = threadIdx.x;

    size_t qbase = (size_t)np * 64 * QKVC;

    // load q (scaled)
    #pragma unroll
    for (int i = 0; i < 8; i++) {
        int id = t + i * 256; int qp = id >> 5, d = id & 31;
        qs[qp * 33 + d] = g_qkv[qbase + (size_t)qp * QKVC + m * 32 + d] * ATTN_SCALE;
    }
    // load k of 4 routed windows
    const int* rs = g_ridx + np * 4;
    #pragma unroll
    for (int wsel = 0; wsel < 4; wsel++) {
        size_t kb = (size_t)(n * 49 + rs[wsel]) * 64 * QKVC;
        #pragma unroll
        for (int i = 0; i < 8; i++) {
            int id = t + i * 256; int kp = id >> 5, d = id & 31;
            kvs[(wsel * 64 + kp) * 33 + d] = g_qkv[kb + (size_t)kp * QKVC + 256 + m * 32 + d];
        }
    }
    __syncthreads();

    // S = q @ k^T  (64x256, K=32), 8x8 register tiles
    {
        int rg = t >> 5, cg = t & 31;
        float acc[8][8];
        #pragma unroll
        for (int i = 0; i < 8; i++)
            #pragma unroll
            for (int j = 0; j < 8; j++) acc[i][j] = 0.f;
        #pragma unroll 4
        for (int dd = 0; dd < 32; dd++) {
            float a[8], bb[8];
            #pragma unroll
            for (int i = 0; i < 8; i++) a[i]  = qs[(rg * 8 + i) * 33 + dd];
            #pragma unroll
            for (int j = 0; j < 8; j++) bb[j] = kvs[(cg + 32 * j) * 33 + dd];
            #pragma unroll
            for (int i = 0; i < 8; i++)
                #pragma unroll
                for (int j = 0; j < 8; j++)
                    acc[i][j] += a[i] * bb[j];
        }
        #pragma unroll
        for (int i = 0; i < 8; i++)
            #pragma unroll
            for (int j = 0; j < 8; j++)
                S[(rg * 8 + i) * 257 + cg + 32 * j] = acc[i][j];
    }
    __syncthreads();

    // load v (overwrite k region)
    #pragma unroll
    for (int wsel = 0; wsel < 4; wsel++) {
        size_t kb = (size_t)(n * 49 + rs[wsel]) * 64 * QKVC;
        #pragma unroll
        for (int i = 0; i < 8; i++) {
            int id = t + i * 256; int kp = id >> 5, d = id & 31;
            kvs[(wsel * 64 + kp) * 33 + d] = g_qkv[kb + (size_t)kp * QKVC + 512 + m * 32 + d];
        }
    }
    // softmax rows (threads 0..63)
    if (t < 64) {
        float* Sr = S + t * 257;
        float mx = -3.4e38f;
        for (int k = 0; k < 256; k++) mx = fmaxf(mx, Sr[k]);
        float sum = 0.f;
        for (int k = 0; k < 256; k++) { float e = __expf(Sr[k] - mx); Sr[k] = e; sum += e; }
        float inv = 1.f / sum;
        for (int k = 0; k < 256; k++) Sr[k] *= inv;
    }
    __syncthreads();

    // O = P @ V  (64x32, K=256), 4 rows x 2 cols per thread
    {
        int rg = t >> 4, cg = t & 15;
        float acc[4][2];
        #pragma unroll
        for (int i = 0; i < 4; i++) { acc[i][0] = 0.f; acc[i][1] = 0.f; }
        for (int kk = 0; kk < 256; kk++) {
            float v0 = kvs[kk * 33 + cg * 2];
            float v1 = kvs[kk * 33 + cg * 2 + 1];
            #pragma unroll
            for (int i = 0; i < 4; i++) {
                float p = S[(rg * 4 + i) * 257 + kk];
                acc[i][0] += p * v0;
                acc[i][1] += p * v1;
            }
        }
        #pragma unroll
        for (int i = 0; i < 4; i++) {
            int row = rg * 4 + i;
            size_t ob = ((size_t)np * 64 + row) * CDIM + m * 32 + cg * 2;
            g_attn[ob]     = acc[i][0];
            g_attn[ob + 1] = acc[i][1];
        }
    }
}

// ---------------------------------------------------------------------------
extern "C" void kernel_launch(void* const* d_in, const int* in_sizes, int n_in,
                              void* d_out, int out_size)
{
    const float* x     = (const float*)d_in[0];
    const float* ln1g  = (const float*)d_in[1];
    const float* ln1b  = (const float*)d_in[2];
    const float* qkvw  = (const float*)d_in[3];
    const float* qkvb  = (const float*)d_in[4];
    const float* lepew = (const float*)d_in[5];
    const float* lepeb = (const float*)d_in[6];
    const float* wow   = (const float*)d_in[7];
    const float* wob   = (const float*)d_in[8];
    const float* ln2g  = (const float*)d_in[9];
    const float* ln2b  = (const float*)d_in[10];
    const float* w1    = (const float*)d_in[11];
    const float* b1    = (const float*)d_in[12];
    const float* w2    = (const float*)d_in[13];
    const float* b2    = (const float*)d_in[14];
    float* out = (float*)d_out;

    float *p_xln, *p_qkv, *p_lepe, *p_attn, *p_x1, *p_hln, *p_hid;
    cudaGetSymbolAddress((void**)&p_xln,  g_xln);
    cudaGetSymbolAddress((void**)&p_qkv,  g_qkv);
    cudaGetSymbolAddress((void**)&p_lepe, g_lepe);
    cudaGetSymbolAddress((void**)&p_attn, g_attn);
    cudaGetSymbolAddress((void**)&p_x1,   g_x1);
    cudaGetSymbolAddress((void**)&p_hln,  g_hln);
    cudaGetSymbolAddress((void**)&p_hid,  g_hid);
    cudaFuncSetAttribute(attn_kernel, cudaFuncAttributeMaxDynamicSharedMemorySize, ATTN_SMEM);

    // 1. LN1 (image -> window layout)
    ln_kernel<true><<<NPIX, 256>>>(x, ln1g, ln1b, p_xln);
    // 2. QKV gemm: (25088x256)@(256x768)
    sgemm_kernel<EPI_NONE, false><<<dim3(QKVC / BN, NPIX / BM), 256>>>(
        p_xln, nullptr, qkvw, qkvb, nullptr, p_qkv, NPIX, QKVC, CDIM);
    // 3. window means of q,k
    winmean_kernel<<<NB * P2, 512>>>();
    // 4. routing top-4
    route_kernel<<<NB, 256>>>();
    // 5. attention per (n,p,head)
    attn_kernel<<<NB * P2 * NHEAD, 256, ATTN_SMEM>>>();
    // 6. lepe depthwise conv
    lepe_kernel<<<NPIX, 256>>>(lepew, lepeb);
    // 7. (attn + lepe) @ Wo + wo_b + x  -> x1 (window layout)
    sgemm_kernel<EPI_WO, true><<<dim3(CDIM / BN, NPIX / BM), 256>>>(
        p_attn, p_lepe, wow, wob, x, p_x1, NPIX, CDIM, CDIM);
    // 8. LN2
    ln_kernel<false><<<NPIX, 256>>>(p_x1, ln2g, ln2b, p_hln);
    // 9. MLP1 + gelu
    sgemm_kernel<EPI_GELU, false><<<dim3(HIDD / BN, NPIX / BM), 256>>>(
        p_hln, nullptr, w1, b1, nullptr, p_hid, NPIX, HIDD, CDIM);
    // 10. MLP2 + x1 -> d_out (image layout)
    sgemm_kernel<EPI_OUT, false><<<dim3(CDIM / BN, NPIX / BM), 256>>>(
        p_hid, nullptr, w2, b2, p_x1, out, NPIX, CDIM, HIDD);
}

// round 2
// speedup vs baseline: 2.0804x; 2.0804x over previous
#include <cuda_runtime.h>
#include <math.h>
#include <stdint.h>

// ---------------------------------------------------------------------------
// BiFormer block. tf32 tensor-core GEMMs + fp32 attention.
// Layouts: "window" rows  r = (n*49 + p)*64 + q   (p = window, q = pixel-in-window)
//          "image"  rows  r = n*3136 + y*56 + x
// ---------------------------------------------------------------------------

#define NB    8
#define HWDIM 56
#define CDIM  256
#define QKD   256
#define NHEAD 8
#define DHEAD 32
#define P2    49
#define W2    64
#define TOPK  4
#define NPIX  (NB*HWDIM*HWDIM)     // 25088
#define QKVC  768
#define HIDD  1024
#define ATTN_SCALE 0.0625f         // 256^-0.5

// scratch (device globals; no allocation allowed)
__device__ float g_xln [NPIX*CDIM];
__device__ float g_qkv [NPIX*QKVC];
__device__ float g_qkwin[NB*P2*512];
__device__ int   g_ridx[NB*P2*TOPK];
__device__ float g_lepe[NPIX*CDIM];
__device__ float g_attn[NPIX*CDIM];
__device__ float g_x1  [NPIX*CDIM];
__device__ float g_hln [NPIX*CDIM];
__device__ float g_hid [NPIX*HIDD];

__device__ __forceinline__ int img_from_win(int r) {
    int n   = r / 3136;
    int rem = r - n * 3136;
    int p = rem >> 6, q = rem & 63;
    int y = ((p / 7) << 3) | (q >> 3);
    int x = ((p % 7) << 3) | (q & 7);
    return n * 3136 + y * 56 + x;
}
__device__ __forceinline__ int win_from_img(int n, int y, int x) {
    int p = (y >> 3) * 7 + (x >> 3);
    int q = ((y & 7) << 3) | (x & 7);
    return (n * 49 + p) * 64 + q;
}

__device__ __forceinline__ uint32_t f2tf(float f) {
    uint32_t u;
    asm("cvt.rna.tf32.f32 %0, %1;" : "=r"(u) : "f"(f));
    return u;
}

// ---------------- LayerNorm (block = one output row in window layout) -------
template<bool REMAP_IN>
__global__ __launch_bounds__(256) void ln_kernel(
    const float* __restrict__ in, const float* __restrict__ gam,
    const float* __restrict__ bet, float* __restrict__ out)
{
    int r = blockIdx.x, c = threadIdx.x;
    int ir = REMAP_IN ? img_from_win(r) : r;
    float v = in[(size_t)ir * CDIM + c];

    __shared__ float red1[8], red2[8];
    float s = v, s2 = v * v;
    #pragma unroll
    for (int o = 16; o; o >>= 1) {
        s  += __shfl_xor_sync(0xffffffffu, s,  o);
        s2 += __shfl_xor_sync(0xffffffffu, s2, o);
    }
    if ((c & 31) == 0) { red1[c >> 5] = s; red2[c >> 5] = s2; }
    __syncthreads();
    if (c == 0) {
        float t1 = 0.f, t2 = 0.f;
        #pragma unroll
        for (int i = 0; i < 8; i++) { t1 += red1[i]; t2 += red2[i]; }
        float mu = t1 * (1.f / CDIM);
        red1[0] = mu;
        red2[0] = t2 * (1.f / CDIM) - mu * mu;
    }
    __syncthreads();
    float mu = red1[0], var = red2[0];
    out[(size_t)r * CDIM + c] = (v - mu) * rsqrtf(var + 1e-6f) * gam[c] + bet[c];
}

// ---------------- tf32 tensor-core GEMM ------------------------------------
// out[M,N] = (A (+A2)) @ W + bias, epilogue variants.
// Tile: 128x128x32. 8 warps in 4(m) x 2(n); warp tile 32x64 = 2x8 m16n8k8.
#define TBM 128
#define TBN 128
#define TBK 32
#define EPI_NONE 0
#define EPI_GELU 1
#define EPI_WO   2   // += res[img_from_win(row)]  (residual in image layout)
#define EPI_OUT  3   // += res[row]; store to image row (final output)

template<int EPI, bool ADDA>
__global__ __launch_bounds__(256) void tgemm_kernel(
    const float* __restrict__ A, const float* __restrict__ A2,
    const float* __restrict__ W, const float* __restrict__ bias,
    const float* __restrict__ res, float* __restrict__ out,
    int M, int N, int K)
{
    __shared__ uint32_t As[TBM][TBK + 4];   // [m][k]
    __shared__ uint32_t Bs[TBK][TBN + 4];   // [k][n]

    int t = threadIdx.x;
    int wid = t >> 5, lane = t & 31;
    int wm = wid >> 1, wn = wid & 1;
    int gid = lane >> 2, tid4 = lane & 3;
    int bm = blockIdx.y * TBM, bn = blockIdx.x * TBN;

    float acc[2][8][4];
    #pragma unroll
    for (int mt = 0; mt < 2; mt++)
        #pragma unroll
        for (int nt = 0; nt < 8; nt++)
            #pragma unroll
            for (int i = 0; i < 4; i++) acc[mt][nt][i] = 0.f;

    int arow0 = t >> 3, akq = (t & 7) << 2;
    int bcq = lane << 2;

    for (int k0 = 0; k0 < K; k0 += TBK) {
        // stage A (128x32), convert to tf32
        #pragma unroll
        for (int l = 0; l < 4; l++) {
            int row = arow0 + l * 32;
            float4 v = *(const float4*)(A + (size_t)(bm + row) * K + k0 + akq);
            if (ADDA) {
                float4 v2 = *(const float4*)(A2 + (size_t)(bm + row) * K + k0 + akq);
                v.x += v2.x; v.y += v2.y; v.z += v2.z; v.w += v2.w;
            }
            As[row][akq + 0] = f2tf(v.x);
            As[row][akq + 1] = f2tf(v.y);
            As[row][akq + 2] = f2tf(v.z);
            As[row][akq + 3] = f2tf(v.w);
        }
        // stage B (32x128), convert to tf32
        #pragma unroll
        for (int l = 0; l < 4; l++) {
            int kr = wid + l * 8;
            float4 v = *(const float4*)(W + (size_t)(k0 + kr) * N + bn + bcq);
            Bs[kr][bcq + 0] = f2tf(v.x);
            Bs[kr][bcq + 1] = f2tf(v.y);
            Bs[kr][bcq + 2] = f2tf(v.z);
            Bs[kr][bcq + 3] = f2tf(v.w);
        }
        __syncthreads();

        #pragma unroll
        for (int ks = 0; ks < 4; ks++) {
            uint32_t af[2][4], bf[8][2];
            #pragma unroll
            for (int mt = 0; mt < 2; mt++) {
                int r = wm * 32 + mt * 16 + gid;
                int kk = ks * 8 + tid4;
                af[mt][0] = As[r][kk];
                af[mt][1] = As[r + 8][kk];
                af[mt][2] = As[r][kk + 4];
                af[mt][3] = As[r + 8][kk + 4];
            }
            #pragma unroll
            for (int nt = 0; nt < 8; nt++) {
                int c = wn * 64 + nt * 8 + gid;
                int kk = ks * 8 + tid4;
                bf[nt][0] = Bs[kk][c];
                bf[nt][1] = Bs[kk + 4][c];
            }
            #pragma unroll
            for (int mt = 0; mt < 2; mt++)
                #pragma unroll
                for (int nt = 0; nt < 8; nt++) {
                    asm volatile(
                        "mma.sync.aligned.m16n8k8.row.col.f32.tf32.tf32.f32 "
                        "{%0,%1,%2,%3}, {%4,%5,%6,%7}, {%8,%9}, {%0,%1,%2,%3};\n"
                        : "+f"(acc[mt][nt][0]), "+f"(acc[mt][nt][1]),
                          "+f"(acc[mt][nt][2]), "+f"(acc[mt][nt][3])
                        : "r"(af[mt][0]), "r"(af[mt][1]), "r"(af[mt][2]), "r"(af[mt][3]),
                          "r"(bf[nt][0]), "r"(bf[nt][1]));
                }
        }
        __syncthreads();
    }

    // epilogue: C[gid][2*tid4], C[gid][2*tid4+1] (half 0), C[gid+8][...] (half 1)
    #pragma unroll
    for (int mt = 0; mt < 2; mt++) {
        #pragma unroll
        for (int half = 0; half < 2; half++) {
            int row  = bm + wm * 32 + mt * 16 + gid + half * 8;
            int rrow = (EPI == EPI_WO)  ? img_from_win(row) : row;
            int orow = (EPI == EPI_OUT) ? img_from_win(row) : row;
            #pragma unroll
            for (int nt = 0; nt < 8; nt++) {
                int col = bn + wn * 64 + nt * 8 + tid4 * 2;
                float v0 = acc[mt][nt][half * 2 + 0] + bias[col];
                float v1 = acc[mt][nt][half * 2 + 1] + bias[col + 1];
                if (EPI == EPI_GELU) {
                    v0 = 0.5f * v0 * (1.f + erff(v0 * 0.70710678118654752f));
                    v1 = 0.5f * v1 * (1.f + erff(v1 * 0.70710678118654752f));
                }
                if (EPI == EPI_WO || EPI == EPI_OUT) {
                    float2 rv = *(const float2*)(res + (size_t)rrow * N + col);
                    v0 += rv.x; v1 += rv.y;
                }
                float2 ov; ov.x = v0; ov.y = v1;
                *(float2*)(out + (size_t)orow * N + col) = ov;
            }
        }
    }
}

// ---------------- window means of q,k -> g_qkwin ----------------------------
__global__ __launch_bounds__(512) void winmean_kernel()
{
    int np = blockIdx.x;            // n*49+p
    int c  = threadIdx.x;           // 0..511 (q:0..255, k:256..511)
    const float* base = g_qkv + (size_t)np * 64 * QKVC;
    float s = 0.f;
    #pragma unroll 8
    for (int q = 0; q < 64; q++) s += base[q * QKVC + c];
    g_qkwin[(size_t)np * 512 + c] = s * (1.f / 64.f);
}

// ---------------- routing: one block per (n,p); warp per candidate ----------
__global__ __launch_bounds__(256) void route_kernel()
{
    int np = blockIdx.x;            // n*49+p
    int n  = np / 49;
    int t  = threadIdx.x, lane = t & 31, w = t >> 5;
    __shared__ float lg[P2];
    const float* qw = g_qkwin + (size_t)np * 512;
    for (int pp = w; pp < P2; pp += 8) {
        const float* kw = g_qkwin + (size_t)(n * 49 + pp) * 512 + 256;
        float s = 0.f;
        #pragma unroll
        for (int c = 0; c < 256; c += 32) s += qw[c + lane] * kw[c + lane];
        #pragma unroll
        for (int o = 16; o; o >>= 1) s += __shfl_xor_sync(0xffffffffu, s, o);
        if (lane == 0) lg[pp] = s;
    }
    __syncthreads();
    if (t == 0) {
        int sel[4] = {-1, -1, -1, -1};
        #pragma unroll
        for (int k = 0; k < 4; k++) {
            float best = -3.4e38f; int bi = 0;
            for (int i = 0; i < P2; i++) {
                if (i == sel[0] || i == sel[1] || i == sel[2] || i == sel[3]) continue;
                if (lg[i] > best) { best = lg[i]; bi = i; }
            }
            sel[k] = bi;
            g_ridx[np * 4 + k] = bi;
        }
    }
}

// ---------------- lepe: 5x5 depthwise conv on v, SAME padding ---------------
__global__ __launch_bounds__(256) void lepe_kernel(
    const float* __restrict__ w, const float* __restrict__ b)
{
    int pix = blockIdx.x, c = threadIdx.x;
    int n = pix / 3136; int rem = pix - n * 3136;
    int y = rem / 56, x = rem - y * 56;
    float acc = b[c];
    #pragma unroll
    for (int dy = 0; dy < 5; dy++) {
        int yy = y + dy - 2;
        if (yy < 0 || yy >= 56) continue;
        #pragma unroll
        for (int dx = 0; dx < 5; dx++) {
            int xx = x + dx - 2;
            if (xx < 0 || xx >= 56) continue;
            int wr = win_from_img(n, yy, xx);
            acc += w[(dy * 5 + dx) * CDIM + c] * g_qkv[(size_t)wr * QKVC + 512 + c];
        }
    }
    g_lepe[(size_t)win_from_img(n, y, x) * CDIM + c] = acc;
}

// ---------------- attention: block = (n,p,head) -----------------------------
#define ATTN_SMEM ((64*33 + 256*33 + 64*257) * 4)

__global__ __launch_bounds__(256) void attn_kernel()
{
    extern __shared__ float sm[];
    float* qs  = sm;                  // 64*33
    float* kvs = sm + 64 * 33;        // 256*33
    float* S   = kvs + 256 * 33;      // 64*257

    int blk = blockIdx.x;
    int m  = blk & 7;
    int np = blk >> 3;                // n*49 + p
    int n  = np / 49;
    int t  = threadIdx.x;

    size_t qbase = (size_t)np * 64 * QKVC;

    #pragma unroll
    for (int i = 0; i < 8; i++) {
        int id = t + i * 256; int qp = id >> 5, d = id & 31;
        qs[qp * 33 + d] = g_qkv[qbase + (size_t)qp * QKVC + m * 32 + d] * ATTN_SCALE;
    }
    const int* rs = g_ridx + np * 4;
    #pragma unroll
    for (int wsel = 0; wsel < 4; wsel++) {
        size_t kb = (size_t)(n * 49 + rs[wsel]) * 64 * QKVC;
        #pragma unroll
        for (int i = 0; i < 8; i++) {
            int id = t + i * 256; int kp = id >> 5, d = id & 31;
            kvs[(wsel * 64 + kp) * 33 + d] = g_qkv[kb + (size_t)kp * QKVC + 256 + m * 32 + d];
        }
    }
    __syncthreads();

    {
        int rg = t >> 5, cg = t & 31;
        float acc[8][8];
        #pragma unroll
        for (int i = 0; i < 8; i++)
            #pragma unroll
            for (int j = 0; j < 8; j++) acc[i][j] = 0.f;
        #pragma unroll 4
        for (int dd = 0; dd < 32; dd++) {
            float a[8], bb[8];
            #pragma unroll
            for (int i = 0; i < 8; i++) a[i]  = qs[(rg * 8 + i) * 33 + dd];
            #pragma unroll
            for (int j = 0; j < 8; j++) bb[j] = kvs[(cg + 32 * j) * 33 + dd];
            #pragma unroll
            for (int i = 0; i < 8; i++)
                #pragma unroll
                for (int j = 0; j < 8; j++)
                    acc[i][j] += a[i] * bb[j];
        }
        #pragma unroll
        for (int i = 0; i < 8; i++)
            #pragma unroll
            for (int j = 0; j < 8; j++)
                S[(rg * 8 + i) * 257 + cg + 32 * j] = acc[i][j];
    }
    __syncthreads();

    #pragma unroll
    for (int wsel = 0; wsel < 4; wsel++) {
        size_t kb = (size_t)(n * 49 + rs[wsel]) * 64 * QKVC;
        #pragma unroll
        for (int i = 0; i < 8; i++) {
            int id = t + i * 256; int kp = id >> 5, d = id & 31;
            kvs[(wsel * 64 + kp) * 33 + d] = g_qkv[kb + (size_t)kp * QKVC + 512 + m * 32 + d];
        }
    }
    if (t < 64) {
        float* Sr = S + t * 257;
        float mx = -3.4e38f;
        for (int k = 0; k < 256; k++) mx = fmaxf(mx, Sr[k]);
        float sum = 0.f;
        for (int k = 0; k < 256; k++) { float e = __expf(Sr[k] - mx); Sr[k] = e; sum += e; }
        float inv = 1.f / sum;
        for (int k = 0; k < 256; k++) Sr[k] *= inv;
    }
    __syncthreads();

    {
        int rg = t >> 4, cg = t & 15;
        float acc[4][2];
        #pragma unroll
        for (int i = 0; i < 4; i++) { acc[i][0] = 0.f; acc[i][1] = 0.f; }
        for (int kk = 0; kk < 256; kk++) {
            float v0 = kvs[kk * 33 + cg * 2];
            float v1 = kvs[kk * 33 + cg * 2 + 1];
            #pragma unroll
            for (int i = 0; i < 4; i++) {
                float p = S[(rg * 4 + i) * 257 + kk];
                acc[i][0] += p * v0;
                acc[i][1] += p * v1;
            }
        }
        #pragma unroll
        for (int i = 0; i < 4; i++) {
            int row = rg * 4 + i;
            size_t ob = ((size_t)np * 64 + row) * CDIM + m * 32 + cg * 2;
            g_attn[ob]     = acc[i][0];
            g_attn[ob + 1] = acc[i][1];
        }
    }
}

// ---------------------------------------------------------------------------
extern "C" void kernel_launch(void* const* d_in, const int* in_sizes, int n_in,
                              void* d_out, int out_size)
{
    const float* x     = (const float*)d_in[0];
    const float* ln1g  = (const float*)d_in[1];
    const float* ln1b  = (const float*)d_in[2];
    const float* qkvw  = (const float*)d_in[3];
    const float* qkvb  = (const float*)d_in[4];
    const float* lepew = (const float*)d_in[5];
    const float* lepeb = (const float*)d_in[6];
    const float* wow   = (const float*)d_in[7];
    const float* wob   = (const float*)d_in[8];
    const float* ln2g  = (const float*)d_in[9];
    const float* ln2b  = (const float*)d_in[10];
    const float* w1    = (const float*)d_in[11];
    const float* b1    = (const float*)d_in[12];
    const float* w2    = (const float*)d_in[13];
    const float* b2    = (const float*)d_in[14];
    float* out = (float*)d_out;

    float *p_xln, *p_qkv, *p_lepe, *p_attn, *p_x1, *p_hln, *p_hid;
    cudaGetSymbolAddress((void**)&p_xln,  g_xln);
    cudaGetSymbolAddress((void**)&p_qkv,  g_qkv);
    cudaGetSymbolAddress((void**)&p_lepe, g_lepe);
    cudaGetSymbolAddress((void**)&p_attn, g_attn);
    cudaGetSymbolAddress((void**)&p_x1,   g_x1);
    cudaGetSymbolAddress((void**)&p_hln,  g_hln);
    cudaGetSymbolAddress((void**)&p_hid,  g_hid);
    cudaFuncSetAttribute(attn_kernel, cudaFuncAttributeMaxDynamicSharedMemorySize, ATTN_SMEM);

    // 1. LN1 (image -> window layout)
    ln_kernel<true><<<NPIX, 256>>>(x, ln1g, ln1b, p_xln);
    // 2. QKV gemm: (25088x256)@(256x768)
    tgemm_kernel<EPI_NONE, false><<<dim3(QKVC / TBN, NPIX / TBM), 256>>>(
        p_xln, nullptr, qkvw, qkvb, nullptr, p_qkv, NPIX, QKVC, CDIM);
    // 3. window means of q,k
    winmean_kernel<<<NB * P2, 512>>>();
    // 4. routing top-4
    route_kernel<<<NB * P2, 256>>>();
    // 5. attention per (n,p,head)
    attn_kernel<<<NB * P2 * NHEAD, 256, ATTN_SMEM>>>();
    // 6. lepe depthwise conv
    lepe_kernel<<<NPIX, 256>>>(lepew, lepeb);
    // 7. (attn + lepe) @ Wo + wo_b + x  -> x1 (window layout)
    tgemm_kernel<EPI_WO, true><<<dim3(CDIM / TBN, NPIX / TBM), 256>>>(
        p_attn, p_lepe, wow, wob, x, p_x1, NPIX, CDIM, CDIM);
    // 8. LN2
    ln_kernel<false><<<NPIX, 256>>>(p_x1, ln2g, ln2b, p_hln);
    // 9. MLP1 + gelu
    tgemm_kernel<EPI_GELU, false><<<dim3(HIDD / TBN, NPIX / TBM), 256>>>(
        p_hln, nullptr, w1, b1, nullptr, p_hid, NPIX, HIDD, CDIM);
    // 10. MLP2 + x1 -> d_out (image layout)
    tgemm_kernel<EPI_OUT, false><<<dim3(CDIM / TBN, NPIX / TBM), 256>>>(
        p_hid, nullptr, w2, b2, p_x1, out, NPIX, CDIM, HIDD);
}

// round 4
// speedup vs baseline: 2.4759x; 1.1901x over previous
#include <cuda_runtime.h>
#include <cuda_fp16.h>
#include <math.h>
#include <stdint.h>

// ---------------------------------------------------------------------------
// BiFormer block. fp16 tensor-core GEMMs + fp16 tensor-core attention.
// "window" rows  r = (n*49 + p)*64 + q ; "image" rows r = n*3136 + y*56 + x
// ---------------------------------------------------------------------------

#define NB    8
#define HWDIM 56
#define CDIM  256
#define NHEAD 8
#define P2    49
#define TOPK  4
#define NPIX  (NB*HWDIM*HWDIM)     // 25088
#define QKVC  768
#define HIDD  1024
#define ATTN_SCALE 0.0625f

__device__ float g_xln [NPIX*CDIM];
__device__ float g_qkv [NPIX*QKVC];
__device__ float g_qkwin[NB*P2*512];
__device__ int   g_ridx[NB*P2*TOPK];
__device__ float g_lepe[NPIX*CDIM];
__device__ float g_attn[NPIX*CDIM];
__device__ float g_x1  [NPIX*CDIM];
__device__ float g_hln [NPIX*CDIM];
__device__ float g_hid [NPIX*HIDD];

__device__ __forceinline__ int img_from_win(int r) {
    int n   = r / 3136;
    int rem = r - n * 3136;
    int p = rem >> 6, q = rem & 63;
    int y = ((p / 7) << 3) | (q >> 3);
    int x = ((p % 7) << 3) | (q & 7);
    return n * 3136 + y * 56 + x;
}
__device__ __forceinline__ int win_from_img(int n, int y, int x) {
    int p = (y >> 3) * 7 + (x >> 3);
    int q = ((y & 7) << 3) | (x & 7);
    return (n * 49 + p) * 64 + q;
}

#define MMA16816(c0,c1,c2,c3,a0,a1,a2,a3,b0,b1)                              \
    asm volatile(                                                             \
        "mma.sync.aligned.m16n8k16.row.col.f32.f16.f16.f32 "                  \
        "{%0,%1,%2,%3}, {%4,%5,%6,%7}, {%8,%9}, {%0,%1,%2,%3};\n"             \
        : "+f"(c0), "+f"(c1), "+f"(c2), "+f"(c3)                              \
        : "r"(a0), "r"(a1), "r"(a2), "r"(a3), "r"(b0), "r"(b1))

// ---------------- LayerNorm -------------------------------------------------
template<bool REMAP_IN>
__global__ __launch_bounds__(256) void ln_kernel(
    const float* __restrict__ in, const float* __restrict__ gam,
    const float* __restrict__ bet, float* __restrict__ out)
{
    int r = blockIdx.x, c = threadIdx.x;
    int ir = REMAP_IN ? img_from_win(r) : r;
    float v = in[(size_t)ir * CDIM + c];

    __shared__ float red1[8], red2[8];
    float s = v, s2 = v * v;
    #pragma unroll
    for (int o = 16; o; o >>= 1) {
        s  += __shfl_xor_sync(0xffffffffu, s,  o);
        s2 += __shfl_xor_sync(0xffffffffu, s2, o);
    }
    if ((c & 31) == 0) { red1[c >> 5] = s; red2[c >> 5] = s2; }
    __syncthreads();
    if (c == 0) {
        float t1 = 0.f, t2 = 0.f;
        #pragma unroll
        for (int i = 0; i < 8; i++) { t1 += red1[i]; t2 += red2[i]; }
        float mu = t1 * (1.f / CDIM);
        red1[0] = mu;
        red2[0] = t2 * (1.f / CDIM) - mu * mu;
    }
    __syncthreads();
    float mu = red1[0], var = red2[0];
    out[(size_t)r * CDIM + c] = (v - mu) * rsqrtf(var + 1e-6f) * gam[c] + bet[c];
}

// ---------------- fp16 tensor-core GEMM -------------------------------------
// Tile 128x128x32, 8 warps (4m x 2n), warp 32x64 = 2x8 m16n8k16 tiles.
#define TBM 128
#define TBN 128
#define TBK 32
#define EPI_NONE 0
#define EPI_GELU 1
#define EPI_WO   2
#define EPI_OUT  3

template<int EPI, bool ADDA>
__global__ __launch_bounds__(256) void hgemm_kernel(
    const float* __restrict__ A, const float* __restrict__ A2,
    const float* __restrict__ W, const float* __restrict__ bias,
    const float* __restrict__ res, float* __restrict__ out,
    int M, int N, int K)
{
    __shared__ __half As[TBM][TBK + 8];   // [m][k]
    __shared__ __half Bs[TBN][TBK + 8];   // [n][k]  (W transposed in smem)

    int t = threadIdx.x;
    int wid = t >> 5, lane = t & 31;
    int wm = wid >> 1, wn = wid & 1;
    int gid = lane >> 2, tid4 = lane & 3;
    int bm = blockIdx.y * TBM, bn = blockIdx.x * TBN;

    float acc[2][8][4];
    #pragma unroll
    for (int mt = 0; mt < 2; mt++)
        #pragma unroll
        for (int nt = 0; nt < 8; nt++)
            #pragma unroll
            for (int i = 0; i < 4; i++) acc[mt][nt][i] = 0.f;

    int arow0 = t >> 3, akq = (t & 7) << 2;    // A: rows arow0+32l, k cols akq..+3
    int bkr = t & 7, bcq = (t >> 3) << 2;      // B: k rows bkr+8l, n cols bcq..+3

    float4 apre[4], bpre[4];
    // prefetch first k tile
    #pragma unroll
    for (int l = 0; l < 4; l++) {
        apre[l] = *(const float4*)(A + (size_t)(bm + arow0 + 32 * l) * K + akq);
        if (ADDA) {
            float4 v2 = *(const float4*)(A2 + (size_t)(bm + arow0 + 32 * l) * K + akq);
            apre[l].x += v2.x; apre[l].y += v2.y; apre[l].z += v2.z; apre[l].w += v2.w;
        }
        bpre[l] = *(const float4*)(W + (size_t)(bkr + 8 * l) * N + bn + bcq);
    }

    for (int k0 = 0; k0 < K; k0 += TBK) {
        // store staged tile (convert to half)
        #pragma unroll
        for (int l = 0; l < 4; l++) {
            int row = arow0 + 32 * l;
            *(half2*)&As[row][akq]     = __floats2half2_rn(apre[l].x, apre[l].y);
            *(half2*)&As[row][akq + 2] = __floats2half2_rn(apre[l].z, apre[l].w);
            int kr = bkr + 8 * l;
            Bs[bcq + 0][kr] = __float2half_rn(bpre[l].x);
            Bs[bcq + 1][kr] = __float2half_rn(bpre[l].y);
            Bs[bcq + 2][kr] = __float2half_rn(bpre[l].z);
            Bs[bcq + 3][kr] = __float2half_rn(bpre[l].w);
        }
        __syncthreads();

        // prefetch next tile
        if (k0 + TBK < K) {
            int kn = k0 + TBK;
            #pragma unroll
            for (int l = 0; l < 4; l++) {
                apre[l] = *(const float4*)(A + (size_t)(bm + arow0 + 32 * l) * K + kn + akq);
                if (ADDA) {
                    float4 v2 = *(const float4*)(A2 + (size_t)(bm + arow0 + 32 * l) * K + kn + akq);
                    apre[l].x += v2.x; apre[l].y += v2.y; apre[l].z += v2.z; apre[l].w += v2.w;
                }
                bpre[l] = *(const float4*)(W + (size_t)(kn + bkr + 8 * l) * N + bn + bcq);
            }
        }

        #pragma unroll
        for (int ks = 0; ks < 2; ks++) {
            uint32_t af[2][4];
            #pragma unroll
            for (int mt = 0; mt < 2; mt++) {
                int r = wm * 32 + mt * 16 + gid;
                int kk = ks * 16 + tid4 * 2;
                af[mt][0] = *(const uint32_t*)&As[r][kk];
                af[mt][1] = *(const uint32_t*)&As[r + 8][kk];
                af[mt][2] = *(const uint32_t*)&As[r][kk + 8];
                af[mt][3] = *(const uint32_t*)&As[r + 8][kk + 8];
            }
            #pragma unroll
            for (int nt = 0; nt < 8; nt++) {
                int c = wn * 64 + nt * 8 + gid;
                int kk = ks * 16 + tid4 * 2;
                uint32_t b0 = *(const uint32_t*)&Bs[c][kk];
                uint32_t b1 = *(const uint32_t*)&Bs[c][kk + 8];
                #pragma unroll
                for (int mt = 0; mt < 2; mt++)
                    MMA16816(acc[mt][nt][0], acc[mt][nt][1], acc[mt][nt][2], acc[mt][nt][3],
                             af[mt][0], af[mt][1], af[mt][2], af[mt][3], b0, b1);
            }
        }
        __syncthreads();
    }

    #pragma unroll
    for (int mt = 0; mt < 2; mt++) {
        #pragma unroll
        for (int half = 0; half < 2; half++) {
            int row  = bm + wm * 32 + mt * 16 + gid + half * 8;
            int rrow = (EPI == EPI_WO)  ? img_from_win(row) : row;
            int orow = (EPI == EPI_OUT) ? img_from_win(row) : row;
            #pragma unroll
            for (int nt = 0; nt < 8; nt++) {
                int col = bn + wn * 64 + nt * 8 + tid4 * 2;
                float v0 = acc[mt][nt][half * 2 + 0] + bias[col];
                float v1 = acc[mt][nt][half * 2 + 1] + bias[col + 1];
                if (EPI == EPI_GELU) {
                    v0 = 0.5f * v0 * (1.f + erff(v0 * 0.70710678118654752f));
                    v1 = 0.5f * v1 * (1.f + erff(v1 * 0.70710678118654752f));
                }
                if (EPI == EPI_WO || EPI == EPI_OUT) {
                    float2 rv = *(const float2*)(res + (size_t)rrow * N + col);
                    v0 += rv.x; v1 += rv.y;
                }
                float2 ov; ov.x = v0; ov.y = v1;
                *(float2*)(out + (size_t)orow * N + col) = ov;
            }
        }
    }
}

// ---------------- window means ----------------------------------------------
__global__ __launch_bounds__(512) void winmean_kernel()
{
    int np = blockIdx.x;
    int c  = threadIdx.x;
    const float* base = g_qkv + (size_t)np * 64 * QKVC;
    float s = 0.f;
    #pragma unroll 8
    for (int q = 0; q < 64; q++) s += base[q * QKVC + c];
    g_qkwin[(size_t)np * 512 + c] = s * (1.f / 64.f);
}

// ---------------- routing ---------------------------------------------------
__global__ __launch_bounds__(256) void route_kernel()
{
    int np = blockIdx.x;
    int n  = np / 49;
    int t  = threadIdx.x, lane = t & 31, w = t >> 5;
    __shared__ float lg[P2];
    const float* qw = g_qkwin + (size_t)np * 512;
    for (int pp = w; pp < P2; pp += 8) {
        const float* kw = g_qkwin + (size_t)(n * 49 + pp) * 512 + 256;
        float s = 0.f;
        #pragma unroll
        for (int c = 0; c < 256; c += 32) s += qw[c + lane] * kw[c + lane];
        #pragma unroll
        for (int o = 16; o; o >>= 1) s += __shfl_xor_sync(0xffffffffu, s, o);
        if (lane == 0) lg[pp] = s;
    }
    __syncthreads();
    if (t == 0) {
        int sel[4] = {-1, -1, -1, -1};
        #pragma unroll
        for (int k = 0; k < 4; k++) {
            float best = -3.4e38f; int bi = 0;
            for (int i = 0; i < P2; i++) {
                if (i == sel[0] || i == sel[1] || i == sel[2] || i == sel[3]) continue;
                if (lg[i] > best) { best = lg[i]; bi = i; }
            }
            sel[k] = bi;
            g_ridx[np * 4 + k] = bi;
        }
    }
}

// ---------------- lepe 5x5 depthwise conv -----------------------------------
__global__ __launch_bounds__(256) void lepe_kernel(
    const float* __restrict__ w, const float* __restrict__ b)
{
    int pix = blockIdx.x, c = threadIdx.x;
    int n = pix / 3136; int rem = pix - n * 3136;
    int y = rem / 56, x = rem - y * 56;
    float acc = b[c];
    #pragma unroll
    for (int dy = 0; dy < 5; dy++) {
        int yy = y + dy - 2;
        if (yy < 0 || yy >= 56) continue;
        #pragma unroll
        for (int dx = 0; dx < 5; dx++) {
            int xx = x + dx - 2;
            if (xx < 0 || xx >= 56) continue;
            int wr = win_from_img(n, yy, xx);
            acc += w[(dy * 5 + dx) * CDIM + c] * g_qkv[(size_t)wr * QKVC + 512 + c];
        }
    }
    g_lepe[(size_t)win_from_img(n, y, x) * CDIM + c] = acc;
}

// ---------------- attention (tensor core): block = (n,p,head) ---------------
// smem: Qs half[64][40], Ks half[256][40], Sf float[64][260],
//       Ph half[64][264], Vt half[32][264]
#define QS_LD 40
#define KS_LD 40
#define SF_LD 260
#define PH_LD 264
#define VT_LD 264
#define OFF_QS 0
#define OFF_KS (OFF_QS + 64*QS_LD)                 // halves
#define OFF_SF_B (((OFF_KS + 256*KS_LD)*2 + 15) & ~15)  // bytes, 16B align
#define OFF_PH_B (OFF_SF_B + 64*SF_LD*4)
#define OFF_VT_B (OFF_PH_B + 64*PH_LD*2)
#define ATTN_SMEM (OFF_VT_B + 32*VT_LD*2 + 16)

__global__ __launch_bounds__(256) void attn_kernel()
{
    extern __shared__ char smraw[];
    __half* Qs = (__half*)smraw;
    __half* Ks = Qs + OFF_KS;
    float*  Sf = (float*)(smraw + OFF_SF_B);
    __half* Ph = (__half*)(smraw + OFF_PH_B);
    __half* Vt = (__half*)(smraw + OFF_VT_B);

    int blk = blockIdx.x;
    int hd = blk & 7;
    int np = blk >> 3;
    int n  = np / 49;
    int t  = threadIdx.x;
    int wid = t >> 5, lane = t & 31;
    int gid = lane >> 2, tid4 = lane & 3;

    size_t qbase = (size_t)np * 64 * QKVC;
    const int* rs = g_ridx + np * 4;

    // stage Q (scaled, half)
    #pragma unroll
    for (int i = 0; i < 8; i++) {
        int id = t + i * 256; int qp = id >> 5, d = id & 31;
        Qs[qp * QS_LD + d] = __float2half_rn(
            g_qkv[qbase + (size_t)qp * QKVC + hd * 32 + d] * ATTN_SCALE);
    }
    // stage K [keypix][d] and V transposed [d][keypix]
    #pragma unroll
    for (int wsel = 0; wsel < 4; wsel++) {
        size_t kb = (size_t)(n * 49 + rs[wsel]) * 64 * QKVC;
        #pragma unroll
        for (int i = 0; i < 8; i++) {
            int id = t + i * 256; int kp = id >> 5, d = id & 31;
            Ks[(wsel * 64 + kp) * KS_LD + d] =
                __float2half_rn(g_qkv[kb + (size_t)kp * QKVC + 256 + hd * 32 + d]);
            Vt[d * VT_LD + wsel * 64 + kp] =
                __float2half_rn(g_qkv[kb + (size_t)kp * QKVC + 512 + hd * 32 + d]);
        }
    }
    __syncthreads();

    // S = Q @ K^T : m=64, n=256, k=32. Warp w: m-tile w>>1, n-tiles (w&1)*16+nt
    {
        int m0 = (wid >> 1) * 16;
        int nbase = (wid & 1) * 128;
        float acc[16][4];
        #pragma unroll
        for (int nt = 0; nt < 16; nt++)
            #pragma unroll
            for (int i = 0; i < 4; i++) acc[nt][i] = 0.f;
        #pragma unroll
        for (int ks = 0; ks < 2; ks++) {
            int kk = ks * 16 + tid4 * 2;
            uint32_t a0 = *(const uint32_t*)&Qs[(m0 + gid) * QS_LD + kk];
            uint32_t a1 = *(const uint32_t*)&Qs[(m0 + gid + 8) * QS_LD + kk];
            uint32_t a2 = *(const uint32_t*)&Qs[(m0 + gid) * QS_LD + kk + 8];
            uint32_t a3 = *(const uint32_t*)&Qs[(m0 + gid + 8) * QS_LD + kk + 8];
            #pragma unroll
            for (int nt = 0; nt < 16; nt++) {
                int c = nbase + nt * 8 + gid;
                uint32_t b0 = *(const uint32_t*)&Ks[c * KS_LD + kk];
                uint32_t b1 = *(const uint32_t*)&Ks[c * KS_LD + kk + 8];
                MMA16816(acc[nt][0], acc[nt][1], acc[nt][2], acc[nt][3],
                         a0, a1, a2, a3, b0, b1);
            }
        }
        #pragma unroll
        for (int nt = 0; nt < 16; nt++) {
            int c = nbase + nt * 8 + tid4 * 2;
            Sf[(m0 + gid) * SF_LD + c]       = acc[nt][0];
            Sf[(m0 + gid) * SF_LD + c + 1]   = acc[nt][1];
            Sf[(m0 + gid + 8) * SF_LD + c]     = acc[nt][2];
            Sf[(m0 + gid + 8) * SF_LD + c + 1] = acc[nt][3];
        }
    }
    __syncthreads();

    // softmax: 4 threads per row, 64 cols each (strided by 4)
    {
        int row = t >> 2, sub = t & 3;
        const float* Sr = Sf + row * SF_LD;
        float mx = -3.4e38f;
        #pragma unroll 16
        for (int j = 0; j < 64; j++) mx = fmaxf(mx, Sr[sub + j * 4]);
        mx = fmaxf(mx, __shfl_xor_sync(0xffffffffu, mx, 1));
        mx = fmaxf(mx, __shfl_xor_sync(0xffffffffu, mx, 2));
        float e[64];
        float sum = 0.f;
        #pragma unroll 16
        for (int j = 0; j < 64; j++) { e[j] = __expf(Sr[sub + j * 4] - mx); sum += e[j]; }
        sum += __shfl_xor_sync(0xffffffffu, sum, 1);
        sum += __shfl_xor_sync(0xffffffffu, sum, 2);
        float inv = 1.f / sum;
        __half* Pr = Ph + row * PH_LD;
        #pragma unroll 16
        for (int j = 0; j < 64; j++) Pr[sub + j * 4] = __float2half_rn(e[j] * inv);
    }
    __syncthreads();

    // O = P @ V : m=64, n=32, k=256. Warp w: m-tile w>>1, n-tiles (w&1)*2+{0,1}
    {
        int m0 = (wid >> 1) * 16;
        int nbase = (wid & 1) * 16;
        float acc[2][4];
        #pragma unroll
        for (int nt = 0; nt < 2; nt++)
            #pragma unroll
            for (int i = 0; i < 4; i++) acc[nt][i] = 0.f;
        #pragma unroll 4
        for (int ks = 0; ks < 16; ks++) {
            int kk = ks * 16 + tid4 * 2;
            uint32_t a0 = *(const uint32_t*)&Ph[(m0 + gid) * PH_LD + kk];
            uint32_t a1 = *(const uint32_t*)&Ph[(m0 + gid + 8) * PH_LD + kk];
            uint32_t a2 = *(const uint32_t*)&Ph[(m0 + gid) * PH_LD + kk + 8];
            uint32_t a3 = *(const uint32_t*)&Ph[(m0 + gid + 8) * PH_LD + kk + 8];
            #pragma unroll
            for (int nt = 0; nt < 2; nt++) {
                int c = nbase + nt * 8 + gid;
                uint32_t b0 = *(const uint32_t*)&Vt[c * VT_LD + kk];
                uint32_t b1 = *(const uint32_t*)&Vt[c * VT_LD + kk + 8];
                MMA16816(acc[nt][0], acc[nt][1], acc[nt][2], acc[nt][3],
                         a0, a1, a2, a3, b0, b1);
            }
        }
        #pragma unroll
        for (int nt = 0; nt < 2; nt++) {
            int col = hd * 32 + nbase + nt * 8 + tid4 * 2;
            size_t r0 = ((size_t)np * 64 + m0 + gid) * CDIM + col;
            size_t r1 = ((size_t)np * 64 + m0 + gid + 8) * CDIM + col;
            float2 o0; o0.x = acc[nt][0]; o0.y = acc[nt][1];
            float2 o1; o1.x = acc[nt][2]; o1.y = acc[nt][3];
            *(float2*)(g_attn + r0) = o0;
            *(float2*)(g_attn + r1) = o1;
        }
    }
}

// ---------------------------------------------------------------------------
extern "C" void kernel_launch(void* const* d_in, const int* in_sizes, int n_in,
                              void* d_out, int out_size)
{
    const float* x     = (const float*)d_in[0];
    const float* ln1g  = (const float*)d_in[1];
    const float* ln1b  = (const float*)d_in[2];
    const float* qkvw  = (const float*)d_in[3];
    const float* qkvb  = (const float*)d_in[4];
    const float* lepew = (const float*)d_in[5];
    const float* lepeb = (const float*)d_in[6];
    const float* wow   = (const float*)d_in[7];
    const float* wob   = (const float*)d_in[8];
    const float* ln2g  = (const float*)d_in[9];
    const float* ln2b  = (const float*)d_in[10];
    const float* w1    = (const float*)d_in[11];
    const float* b1    = (const float*)d_in[12];
    const float* w2    = (const float*)d_in[13];
    const float* b2    = (const float*)d_in[14];
    float* out = (float*)d_out;

    float *p_xln, *p_qkv, *p_lepe, *p_attn, *p_x1, *p_hln, *p_hid;
    cudaGetSymbolAddress((void**)&p_xln,  g_xln);
    cudaGetSymbolAddress((void**)&p_qkv,  g_qkv);
    cudaGetSymbolAddress((void**)&p_lepe, g_lepe);
    cudaGetSymbolAddress((void**)&p_attn, g_attn);
    cudaGetSymbolAddress((void**)&p_x1,   g_x1);
    cudaGetSymbolAddress((void**)&p_hln,  g_hln);
    cudaGetSymbolAddress((void**)&p_hid,  g_hid);
    cudaFuncSetAttribute(attn_kernel, cudaFuncAttributeMaxDynamicSharedMemorySize, ATTN_SMEM);

    ln_kernel<true><<<NPIX, 256>>>(x, ln1g, ln1b, p_xln);
    hgemm_kernel<EPI_NONE, false><<<dim3(QKVC / TBN, NPIX / TBM), 256>>>(
        p_xln, nullptr, qkvw, qkvb, nullptr, p_qkv, NPIX, QKVC, CDIM);
    winmean_kernel<<<NB * P2, 512>>>();
    route_kernel<<<NB * P2, 256>>>();
    attn_kernel<<<NB * P2 * NHEAD, 256, ATTN_SMEM>>>();
    lepe_kernel<<<NPIX, 256>>>(lepew, lepeb);
    hgemm_kernel<EPI_WO, true><<<dim3(CDIM / TBN, NPIX / TBM), 256>>>(
        p_attn, p_lepe, wow, wob, x, p_x1, NPIX, CDIM, CDIM);
    ln_kernel<false><<<NPIX, 256>>>(p_x1, ln2g, ln2b, p_hln);
    hgemm_kernel<EPI_GELU, false><<<dim3(HIDD / TBN, NPIX / TBM), 256>>>(
        p_hln, nullptr, w1, b1, nullptr, p_hid, NPIX, HIDD, CDIM);
    hgemm_kernel<EPI_OUT, false><<<dim3(CDIM / TBN, NPIX / TBM), 256>>>(
        p_hid, nullptr, w2, b2, p_x1, out, NPIX, CDIM, HIDD);
}